// round 7
// baseline (speedup 1.0000x reference)
#include <cuda_runtime.h>
#include <math.h>

#define GSZ   200
#define G2    40000
#define NPT   128
#define KB    10     // grid cells per block (divides GSZ -> one lat row per block)

typedef unsigned long long u64;

__device__ int g_best;   // packed (num<<16)|(39999-k); reset to 0 by kfinal

// ---------------- f32x2 helpers --------------------------------------------
__device__ __forceinline__ u64 pk(float a, float b) {
    u64 r; asm("mov.b64 %0, {%1, %2};" : "=l"(r) : "f"(a), "f"(b)); return r;
}
__device__ __forceinline__ void upk(u64 v, float& a, float& b) {
    asm("mov.b64 {%0, %1}, %2;" : "=f"(a), "=f"(b) : "l"(v));
}
__device__ __forceinline__ u64 fma2(u64 a, u64 b, u64 c) {
    u64 r; asm("fma.rn.f32x2 %0, %1, %2, %3;" : "=l"(r) : "l"(a), "l"(b), "l"(c)); return r;
}
__device__ __forceinline__ u64 mul2(u64 a, u64 b) {
    u64 r; asm("mul.rn.f32x2 %0, %1, %2;" : "=l"(r) : "l"(a), "l"(b)); return r;
}

// ---------------------------------------------------------------------------
// XLA f32 tanh (Eigen rational) — exact scalar form (used in kfinal only)
// ---------------------------------------------------------------------------
__device__ __forceinline__ float xla_tanh(float x) {
    const float kClamp = 7.90531110763549805f;
    float xc = fminf(fmaxf(x, -kClamp), kClamp);
    float x2 = xc * xc;
    float p = fmaf(x2, -2.76076847742355e-16f, 2.00018790482477e-13f);
    p = fmaf(x2, p, -8.60467152213735e-11f);
    p = fmaf(x2, p,  5.12229709037114e-08f);
    p = fmaf(x2, p,  1.48572235717979e-05f);
    p = fmaf(x2, p,  6.37261928875436e-04f);
    p = fmaf(x2, p,  4.89352455891786e-03f);
    float q = fmaf(x2, 1.19825839466702e-06f, 1.18534705686654e-04f);
    q = fmaf(x2, q, 2.26843463243900e-03f);
    q = fmaf(x2, q, 4.89352518554385e-03f);
    float r = (xc * p) / q;
    return (fabsf(x) < 0.0004f) ? x : r;
}

// Packed-pair tanh with fast division (~2^-22 rel err; knum only).
struct TC { u64 A0,A1,A2,A3,A4,A5,A6, B0,B1,B2,B3; };
__device__ __forceinline__ TC make_tc() {
    TC c;
    c.A0 = pk(-2.76076847742355e-16f, -2.76076847742355e-16f);
    c.A1 = pk( 2.00018790482477e-13f,  2.00018790482477e-13f);
    c.A2 = pk(-8.60467152213735e-11f, -8.60467152213735e-11f);
    c.A3 = pk( 5.12229709037114e-08f,  5.12229709037114e-08f);
    c.A4 = pk( 1.48572235717979e-05f,  1.48572235717979e-05f);
    c.A5 = pk( 6.37261928875436e-04f,  6.37261928875436e-04f);
    c.A6 = pk( 4.89352455891786e-03f,  4.89352455891786e-03f);
    c.B0 = pk( 1.19825839466702e-06f,  1.19825839466702e-06f);
    c.B1 = pk( 1.18534705686654e-04f,  1.18534705686654e-04f);
    c.B2 = pk( 2.26843463243900e-03f,  2.26843463243900e-03f);
    c.B3 = pk( 4.89352518554385e-03f,  4.89352518554385e-03f);
    return c;
}
__device__ __forceinline__ void tanh2f(const TC& C, float z0, float z1,
                                       float& o0, float& o1) {
    const float kClamp = 7.90531110763549805f;
    float x0 = fminf(fmaxf(z0, -kClamp), kClamp);
    float x1 = fminf(fmaxf(z1, -kClamp), kClamp);
    u64 xc = pk(x0, x1);
    u64 x2 = mul2(xc, xc);
    u64 p = fma2(x2, C.A0, C.A1);
    p = fma2(x2, p, C.A2);
    p = fma2(x2, p, C.A3);
    p = fma2(x2, p, C.A4);
    p = fma2(x2, p, C.A5);
    p = fma2(x2, p, C.A6);
    u64 q = fma2(x2, C.B0, C.B1);
    q = fma2(x2, q, C.B2);
    q = fma2(x2, q, C.B3);
    u64 num = mul2(xc, p);
    float n0, n1, q0, q1;
    upk(num, n0, n1); upk(q, q0, q1);
    o0 = __fdividef(n0, q0);           // fast div; q > 4.8e-3 always
    o1 = __fdividef(n1, q1);
}

__device__ __forceinline__ float grid_lon_f(int k) {
    const float dlon = (float)((109.4132 - 95.987) / 200.0);
    return __fadd_rn(95.987f, __fmul_rn(dlon, (float)(k % GSZ)));
}
__device__ __forceinline__ float grid_lat_f(int k) {
    const float dlat = (float)((42.879 - 31.3039) / 200.0);
    return __fadd_rn(31.3039f, __fmul_rn(dlat, (float)(k / GSZ)));
}

#define D2R ((float)(3.14159265358979323846 / 180.0))

// ---------------------------------------------------------------------------
// Kernel 1: per-grid-cell agreement counts + fused packed-argmax atomic.
// ---------------------------------------------------------------------------
__global__ __launch_bounds__(128)
void knum(const float* __restrict__ x,
          const float* __restrict__ w1, const float* __restrict__ b1,
          const float* __restrict__ g1, const float* __restrict__ be1,
          const float* __restrict__ m1, const float* __restrict__ v1,
          const float* __restrict__ w2, const float* __restrict__ b2,
          const float* __restrict__ g2, const float* __restrict__ be2,
          const float* __restrict__ m2, const float* __restrict__ v2,
          const float* __restrict__ w3, const float* __restrict__ b3)
{
    __shared__ __align__(16) float w2s[32][32];   // [i][j] = a2[j]*w2[i*32+j]
    __shared__ __align__(16) float o2s[32];
    __shared__ float u1s[32], u2s[32], u0s[32];
    __shared__ u64  w3p01[32], w3p23[32];
    __shared__ float w3l[32], b3s[8];
    __shared__ int   wsum[KB][4];                 // per-cell, per-warp counts

    const int t = threadIdx.x;

    if (t < 32) {
        float a1 = g1[t] / sqrtf(v1[t] + 1e-5f);
        u1s[t] = a1 * w1[t];
        u2s[t] = a1 * w1[32 + t];
        u0s[t] = fmaf(a1, b1[t], be1[t] - a1 * m1[t]);
        float a2 = g2[t] / sqrtf(v2[t] + 1e-5f);
        o2s[t] = fmaf(a2, b2[t], be2[t] - a2 * m2[t]);
        for (int i = 0; i < 32; i++) w2s[i][t] = a2 * w2[i * 32 + t];
        w3p01[t] = pk(w3[t * 5 + 0], w3[t * 5 + 1]);
        w3p23[t] = pk(w3[t * 5 + 2], w3[t * 5 + 3]);
        w3l[t]   = w3[t * 5 + 4];
        if (t < 5) b3s[t] = b3[t];
    }
    __syncthreads();

    // Per-point precompute.
    float lon2 = x[t * 4 + 0] * D2R;
    float lat2 = x[t * 4 + 1] * D2R;
    float s2 = sinf(lat2), c2 = cosf(lat2);
    float tc = x[t * 4 + 2] / 100.0f;
    int   pt = (int)x[t * 4 + 3];

    float p1[32];
#pragma unroll
    for (int j = 0; j < 32; j++) p1[j] = fmaf(tc, u2s[j], u0s[j]);

    const TC C = make_tc();
    const int lane = t & 31, wid = t >> 5;
    const int kbase = blockIdx.x * KB;

    // Row-constant haversine terms (all KB cells share one lat row).
    float lat1 = grid_lat_f(kbase) * D2R;
    float s1 = sinf(lat1), c1 = cosf(lat1);
    float t1 = c1 * s2, t2 = s1 * c2;     // B = t1 - t2*cdl
    float t3 = s1 * s2, t4 = c1 * c2;     // xv = t3 + t4*cdl

    const u64 lg01_0 = pk(b3s[0], b3s[1]);
    const u64 lg23_0 = pk(b3s[2], b3s[3]);
    const float lg4_0 = b3s[4];

#pragma unroll 1
    for (int kk = 0; kk < KB; kk++) {
        int k = kbase + kk;
        float lon1 = grid_lon_f(k) * D2R;
        float dl = lon2 - lon1;
        float sdl, cdl;
        __sincosf(dl, &sdl, &cdl);         // |dl| < 0.25 rad, fast path safe
        float A  = c2 * sdl;
        float B  = t1 - t2 * cdl;
        float yv = sqrtf(A * A + B * B);
        float xv = t3 + t4 * cdl;
        float gd = atan2f(yv, xv) * 6371.0f;
        float d  = gd / 100.0f;

        // layer 1 (output-pair packed tanh)
        float h1[32];
#pragma unroll
        for (int jj = 0; jj < 16; jj++) {
            float z0 = fmaf(d, u1s[2 * jj + 0], p1[2 * jj + 0]);
            float z1 = fmaf(d, u1s[2 * jj + 1], p1[2 * jj + 1]);
            tanh2f(C, z0, z1, h1[2 * jj], h1[2 * jj + 1]);
        }

        // layer 2: acc over output pairs, sequential i
        u64 acc[16];
        const u64* o2p = (const u64*)o2s;
#pragma unroll
        for (int jj = 0; jj < 16; jj++) acc[jj] = o2p[jj];
#pragma unroll
        for (int i = 0; i < 32; i++) {
            u64 hd = pk(h1[i], h1[i]);
            const u64* wrow = (const u64*)(w2s[i]);
#pragma unroll
            for (int jj = 0; jj < 16; jj++)
                acc[jj] = fma2(hd, wrow[jj], acc[jj]);
        }

        // layer-2 tanh + logits (class-pair packed)
        u64 lg01 = lg01_0, lg23 = lg23_0;
        float lg4 = lg4_0;
#pragma unroll
        for (int jj = 0; jj < 16; jj++) {
            float a0, a1v;
            upk(acc[jj], a0, a1v);
            float h20, h21;
            tanh2f(C, a0, a1v, h20, h21);
            u64 hd0 = pk(h20, h20);
            u64 hd1 = pk(h21, h21);
            lg01 = fma2(hd0, w3p01[2 * jj + 0], lg01);
            lg23 = fma2(hd0, w3p23[2 * jj + 0], lg23);
            lg4  = fmaf(h20, w3l[2 * jj + 0], lg4);
            lg01 = fma2(hd1, w3p01[2 * jj + 1], lg01);
            lg23 = fma2(hd1, w3p23[2 * jj + 1], lg23);
            lg4  = fmaf(h21, w3l[2 * jj + 1], lg4);
        }

        float l0, l1, l2v, l3;
        upk(lg01, l0, l1);
        upk(lg23, l2v, l3);

        // first-max argmax over 5 logits
        int pid = 0; float bb = l0;
        if (l1  > bb) { bb = l1;  pid = 1; }
        if (l2v > bb) { bb = l2v; pid = 2; }
        if (l3  > bb) { bb = l3;  pid = 3; }
        if (lg4 > bb) { bb = lg4; pid = 4; }

        unsigned bal = __ballot_sync(0xffffffffu, pid == pt);
        if (lane == 0) wsum[kk][wid] = __popc(bal);   // disjoint slots, no barrier
    }

    __syncthreads();                                  // one barrier for all cells
    if (t == 0) {
        int bestEnc = 0;
#pragma unroll
        for (int kk = 0; kk < KB; kk++) {
            int cnt = wsum[kk][0] + wsum[kk][1] + wsum[kk][2] + wsum[kk][3];
            int enc = (cnt << 16) | (G2 - 1 - (kbase + kk));
            if (enc > bestEnc) bestEnc = enc;
        }
        atomicMax(&g_best, bestEnc);
    }
}

// ---------------------------------------------------------------------------
// Kernel 2: decode best cell + finalize outputs (and reset g_best).
// All weights staged in smem (bit-identical math; kills serial LDG chain).
// out: [0..127] class_, [128..383] ph (N x 2), [384] max_num, [385..386] pos
// ---------------------------------------------------------------------------
__global__ __launch_bounds__(128)
void kfinal(const float* __restrict__ x,
            const float* __restrict__ w1, const float* __restrict__ b1,
            const float* __restrict__ g1, const float* __restrict__ be1,
            const float* __restrict__ m1, const float* __restrict__ v1,
            const float* __restrict__ w2, const float* __restrict__ b2,
            const float* __restrict__ g2, const float* __restrict__ be2,
            const float* __restrict__ m2, const float* __restrict__ v2,
            const float* __restrict__ w3, const float* __restrict__ b3,
            float* __restrict__ out)
{
    __shared__ float w2sh[1024], w1sh[64], w3sh[160];
    __shared__ float b1s[32], g1s[32], be1s[32], m1s[32], v1s[32];
    __shared__ float b2s[32], g2s[32], be2s[32], m2s[32], v2s[32];
    __shared__ float b3s[5];
    __shared__ int sbest;
    const int t = threadIdx.x;

    if (t == 0) {
        sbest = g_best;
        g_best = 0;              // reset for next graph replay (deterministic)
    }
#pragma unroll
    for (int i = t; i < 1024; i += 128) w2sh[i] = w2[i];
    if (t < 64) w1sh[t] = w1[t];
    if (t < 32) {
        b1s[t] = b1[t]; g1s[t] = g1[t]; be1s[t] = be1[t]; m1s[t] = m1[t]; v1s[t] = v1[t];
        b2s[t] = b2[t]; g2s[t] = g2[t]; be2s[t] = be2[t]; m2s[t] = m2[t]; v2s[t] = v2[t];
    }
    for (int i = t; i < 160; i += 128) w3sh[i] = w3[i];
    if (t < 5) b3s[t] = b3[t];
    __syncthreads();

    const int best = sbest;
    const int bk = (G2 - 1) - (best & 0xFFFF);
    const int bn = best >> 16;

    if (t == 0) {
        out[384] = (float)bn;
        out[385] = grid_lon_f(bk);
        out[386] = grid_lat_f(bk);
    }

    {
        float lon2 = x[t * 4 + 0] * D2R;
        float lat2 = x[t * 4 + 1] * D2R;
        float s2 = sinf(lat2), c2 = cosf(lat2);
        float tc = x[t * 4 + 2] / 100.0f;

        float lat1 = grid_lat_f(bk) * D2R;
        float lon1 = grid_lon_f(bk) * D2R;
        float s1 = sinf(lat1), c1 = cosf(lat1);
        float dl  = lon2 - lon1;
        float sdl = sinf(dl), cdl = cosf(dl);
        float A  = c2 * sdl;
        float B  = c1 * s2 - s1 * c2 * cdl;
        float yv = sqrtf(A * A + B * B);
        float xv = s1 * s2 + c1 * c2 * cdl;
        float gd = atan2f(yv, xv) * 6371.0f;
        float d  = gd / 100.0f;

        float h1[32];
#pragma unroll
        for (int j = 0; j < 32; j++) {
            float z = d * w1sh[j] + tc * w1sh[32 + j] + b1s[j];
            z = g1s[j] * (z - m1s[j]) / sqrtf(v1s[j] + 1e-5f) + be1s[j];
            h1[j] = xla_tanh(z);
        }
        float h2[32];
#pragma unroll
        for (int j = 0; j < 32; j++) {
            float z = b2s[j];
#pragma unroll
            for (int i = 0; i < 32; i++) z += h1[i] * w2sh[i * 32 + j];
            z = g2s[j] * (z - m2s[j]) / sqrtf(v2s[j] + 1e-5f) + be2s[j];
            h2[j] = xla_tanh(z);
        }
        float lg[5];
#pragma unroll
        for (int c = 0; c < 5; c++) {
            float z = b3s[c];
#pragma unroll
            for (int j = 0; j < 32; j++) z += h2[j] * w3sh[j * 5 + c];
            lg[c] = z;
        }
        int pid = 0; float bb = lg[0];
#pragma unroll
        for (int c = 1; c < 5; c++) if (lg[c] > bb) { bb = lg[c]; pid = c; }

        out[t] = (float)pid;
        out[128 + 2 * t + 0] = d * 100.0f;
        out[128 + 2 * t + 1] = tc * 100.0f;
    }
}

// ---------------------------------------------------------------------------
extern "C" void kernel_launch(void* const* d_in, const int* in_sizes, int n_in,
                              void* d_out, int out_size)
{
    const float* x   = (const float*)d_in[0];
    const float* w1  = (const float*)d_in[1];
    const float* b1  = (const float*)d_in[2];
    const float* g1  = (const float*)d_in[3];
    const float* be1 = (const float*)d_in[4];
    const float* m1  = (const float*)d_in[5];
    const float* v1  = (const float*)d_in[6];
    const float* w2  = (const float*)d_in[7];
    const float* b2  = (const float*)d_in[8];
    const float* g2  = (const float*)d_in[9];
    const float* be2 = (const float*)d_in[10];
    const float* m2  = (const float*)d_in[11];
    const float* v2  = (const float*)d_in[12];
    const float* w3  = (const float*)d_in[13];
    const float* b3  = (const float*)d_in[14];
    float* out = (float*)d_out;

    knum<<<G2 / KB, 128>>>(x, w1, b1, g1, be1, m1, v1,
                           w2, b2, g2, be2, m2, v2, w3, b3);
    kfinal<<<1, 128>>>(x, w1, b1, g1, be1, m1, v1,
                       w2, b2, g2, be2, m2, v2, w3, b3, out);
}

// round 8
// speedup vs baseline: 9.9271x; 9.9271x over previous
#include <cuda_runtime.h>
#include <math.h>

#define GSZ   200
#define G2    40000
#define NPT   128
#define KB    10     // grid cells per block (divides GSZ -> one lat row per block)

typedef unsigned long long u64;

__device__ int g_best;   // packed (num<<16)|(39999-k); reset to 0 by kfinal

// ---------------- f32x2 helpers (per-element IEEE rn) -----------------------
__device__ __forceinline__ u64 pk(float a, float b) {
    u64 r; asm("mov.b64 %0, {%1, %2};" : "=l"(r) : "f"(a), "f"(b)); return r;
}
__device__ __forceinline__ void upk(u64 v, float& a, float& b) {
    asm("mov.b64 {%0, %1}, %2;" : "=f"(a), "=f"(b) : "l"(v));
}
__device__ __forceinline__ u64 fma2(u64 a, u64 b, u64 c) {
    u64 r; asm("fma.rn.f32x2 %0, %1, %2, %3;" : "=l"(r) : "l"(a), "l"(b), "l"(c)); return r;
}
__device__ __forceinline__ u64 mul2(u64 a, u64 b) {
    u64 r; asm("mul.rn.f32x2 %0, %1, %2;" : "=l"(r) : "l"(a), "l"(b)); return r;
}

// ---------------------------------------------------------------------------
// XLA f32 tanh (Eigen rational) — exact scalar form (kfinal only)
// ---------------------------------------------------------------------------
__device__ __forceinline__ float xla_tanh(float x) {
    const float kClamp = 7.90531110763549805f;
    float xc = fminf(fmaxf(x, -kClamp), kClamp);
    float x2 = xc * xc;
    float p = fmaf(x2, -2.76076847742355e-16f, 2.00018790482477e-13f);
    p = fmaf(x2, p, -8.60467152213735e-11f);
    p = fmaf(x2, p,  5.12229709037114e-08f);
    p = fmaf(x2, p,  1.48572235717979e-05f);
    p = fmaf(x2, p,  6.37261928875436e-04f);
    p = fmaf(x2, p,  4.89352455891786e-03f);
    float q = fmaf(x2, 1.19825839466702e-06f, 1.18534705686654e-04f);
    q = fmaf(x2, q, 2.26843463243900e-03f);
    q = fmaf(x2, q, 4.89352518554385e-03f);
    float r = (xc * p) / q;
    return (fabsf(x) < 0.0004f) ? x : r;
}

// Packed-pair tanh; SINGLE DELTA vs measured R6: IEEE div -> __fdividef.
struct TC { u64 A0,A1,A2,A3,A4,A5,A6, B0,B1,B2,B3; };
__device__ __forceinline__ TC make_tc() {
    TC c;
    c.A0 = pk(-2.76076847742355e-16f, -2.76076847742355e-16f);
    c.A1 = pk( 2.00018790482477e-13f,  2.00018790482477e-13f);
    c.A2 = pk(-8.60467152213735e-11f, -8.60467152213735e-11f);
    c.A3 = pk( 5.12229709037114e-08f,  5.12229709037114e-08f);
    c.A4 = pk( 1.48572235717979e-05f,  1.48572235717979e-05f);
    c.A5 = pk( 6.37261928875436e-04f,  6.37261928875436e-04f);
    c.A6 = pk( 4.89352455891786e-03f,  4.89352455891786e-03f);
    c.B0 = pk( 1.19825839466702e-06f,  1.19825839466702e-06f);
    c.B1 = pk( 1.18534705686654e-04f,  1.18534705686654e-04f);
    c.B2 = pk( 2.26843463243900e-03f,  2.26843463243900e-03f);
    c.B3 = pk( 4.89352518554385e-03f,  4.89352518554385e-03f);
    return c;
}
__device__ __forceinline__ void tanh2(const TC& C, float z0, float z1,
                                      float& o0, float& o1) {
    const float kClamp = 7.90531110763549805f;
    float x0 = fminf(fmaxf(z0, -kClamp), kClamp);
    float x1 = fminf(fmaxf(z1, -kClamp), kClamp);
    u64 xc = pk(x0, x1);
    u64 x2 = mul2(xc, xc);
    u64 p = fma2(x2, C.A0, C.A1);
    p = fma2(x2, p, C.A2);
    p = fma2(x2, p, C.A3);
    p = fma2(x2, p, C.A4);
    p = fma2(x2, p, C.A5);
    p = fma2(x2, p, C.A6);
    u64 q = fma2(x2, C.B0, C.B1);
    q = fma2(x2, q, C.B2);
    q = fma2(x2, q, C.B3);
    u64 num = mul2(xc, p);
    float n0, n1, q0, q1;
    upk(num, n0, n1); upk(q, q0, q1);
    float r0 = __fdividef(n0, q0);     // fast div (q > 4.8e-3 always)
    float r1 = __fdividef(n1, q1);
    o0 = (fabsf(z0) < 0.0004f) ? z0 : r0;
    o1 = (fabsf(z1) < 0.0004f) ? z1 : r1;
}

__device__ __forceinline__ float grid_lon_f(int k) {
    const float dlon = (float)((109.4132 - 95.987) / 200.0);
    return __fadd_rn(95.987f, __fmul_rn(dlon, (float)(k % GSZ)));
}
__device__ __forceinline__ float grid_lat_f(int k) {
    const float dlat = (float)((42.879 - 31.3039) / 200.0);
    return __fadd_rn(31.3039f, __fmul_rn(dlat, (float)(k / GSZ)));
}

#define D2R ((float)(3.14159265358979323846 / 180.0))

// ---------------------------------------------------------------------------
// Kernel 1: per-grid-cell agreement counts + fused packed-argmax atomic.
// (structure identical to the 645.6us-measured round-6 kernel)
// ---------------------------------------------------------------------------
__global__ __launch_bounds__(128)
void knum(const float* __restrict__ x,
          const float* __restrict__ w1, const float* __restrict__ b1,
          const float* __restrict__ g1, const float* __restrict__ be1,
          const float* __restrict__ m1, const float* __restrict__ v1,
          const float* __restrict__ w2, const float* __restrict__ b2,
          const float* __restrict__ g2, const float* __restrict__ be2,
          const float* __restrict__ m2, const float* __restrict__ v2,
          const float* __restrict__ w3, const float* __restrict__ b3)
{
    __shared__ __align__(16) float w2s[32][32];   // [i][j] = a2[j]*w2[i*32+j]
    __shared__ __align__(16) float o2s[32];
    __shared__ float u1s[32], u2s[32], u0s[32];
    __shared__ u64  w3p01[32], w3p23[32];
    __shared__ float w3l[32], b3s[8];
    __shared__ int   wsum[2][4];

    const int t = threadIdx.x;

    if (t < 32) {
        float a1 = g1[t] / sqrtf(v1[t] + 1e-5f);
        u1s[t] = a1 * w1[t];
        u2s[t] = a1 * w1[32 + t];
        u0s[t] = fmaf(a1, b1[t], be1[t] - a1 * m1[t]);
        float a2 = g2[t] / sqrtf(v2[t] + 1e-5f);
        o2s[t] = fmaf(a2, b2[t], be2[t] - a2 * m2[t]);
        for (int i = 0; i < 32; i++) w2s[i][t] = a2 * w2[i * 32 + t];
        w3p01[t] = pk(w3[t * 5 + 0], w3[t * 5 + 1]);
        w3p23[t] = pk(w3[t * 5 + 2], w3[t * 5 + 3]);
        w3l[t]   = w3[t * 5 + 4];
        if (t < 5) b3s[t] = b3[t];
    }
    __syncthreads();

    // Per-point precompute.
    float lon2 = x[t * 4 + 0] * D2R;
    float lat2 = x[t * 4 + 1] * D2R;
    float s2 = sinf(lat2), c2 = cosf(lat2);
    float tc = x[t * 4 + 2] / 100.0f;
    int   pt = (int)x[t * 4 + 3];

    float p1[32];
#pragma unroll
    for (int j = 0; j < 32; j++) p1[j] = fmaf(tc, u2s[j], u0s[j]);

    const TC C = make_tc();
    const int lane = t & 31, wid = t >> 5;
    const int kbase = blockIdx.x * KB;

    // Row-constant haversine terms (all KB cells share one lat row).
    float lat1 = grid_lat_f(kbase) * D2R;
    float s1 = sinf(lat1), c1 = cosf(lat1);
    float t1 = c1 * s2, t2 = s1 * c2;     // B = t1 - t2*cdl
    float t3 = s1 * s2, t4 = c1 * c2;     // xv = t3 + t4*cdl

    const u64 lg01_0 = pk(b3s[0], b3s[1]);
    const u64 lg23_0 = pk(b3s[2], b3s[3]);
    const float lg4_0 = b3s[4];

    int bestEnc = 0;

#pragma unroll 1
    for (int kk = 0; kk < KB; kk++) {
        int k = kbase + kk;
        float lon1 = grid_lon_f(k) * D2R;
        float dl = lon2 - lon1;
        float sdl, cdl;
        sincosf(dl, &sdl, &cdl);
        float A  = c2 * sdl;
        float B  = t1 - t2 * cdl;
        float yv = sqrtf(A * A + B * B);
        float xv = t3 + t4 * cdl;
        float gd = atan2f(yv, xv) * 6371.0f;
        float d  = gd / 100.0f;

        // layer 1 (output-pair packed tanh)
        float h1[32];
#pragma unroll
        for (int jj = 0; jj < 16; jj++) {
            float z0 = fmaf(d, u1s[2 * jj + 0], p1[2 * jj + 0]);
            float z1 = fmaf(d, u1s[2 * jj + 1], p1[2 * jj + 1]);
            tanh2(C, z0, z1, h1[2 * jj], h1[2 * jj + 1]);
        }

        // layer 2: acc over output pairs, sequential i
        u64 acc[16];
        const u64* o2p = (const u64*)o2s;
#pragma unroll
        for (int jj = 0; jj < 16; jj++) acc[jj] = o2p[jj];
#pragma unroll
        for (int i = 0; i < 32; i++) {
            u64 hd = pk(h1[i], h1[i]);
            const u64* wrow = (const u64*)(w2s[i]);
#pragma unroll
            for (int jj = 0; jj < 16; jj++)
                acc[jj] = fma2(hd, wrow[jj], acc[jj]);
        }

        // layer-2 tanh + logits (class-pair packed)
        u64 lg01 = lg01_0, lg23 = lg23_0;
        float lg4 = lg4_0;
#pragma unroll
        for (int jj = 0; jj < 16; jj++) {
            float a0, a1v;
            upk(acc[jj], a0, a1v);
            float h20, h21;
            tanh2(C, a0, a1v, h20, h21);
            u64 hd0 = pk(h20, h20);
            u64 hd1 = pk(h21, h21);
            lg01 = fma2(hd0, w3p01[2 * jj + 0], lg01);
            lg23 = fma2(hd0, w3p23[2 * jj + 0], lg23);
            lg4  = fmaf(h20, w3l[2 * jj + 0], lg4);
            lg01 = fma2(hd1, w3p01[2 * jj + 1], lg01);
            lg23 = fma2(hd1, w3p23[2 * jj + 1], lg23);
            lg4  = fmaf(h21, w3l[2 * jj + 1], lg4);
        }

        float l0, l1, l2v, l3;
        upk(lg01, l0, l1);
        upk(lg23, l2v, l3);

        // first-max argmax over 5 logits
        int pid = 0; float bb = l0;
        if (l1  > bb) { bb = l1;  pid = 1; }
        if (l2v > bb) { bb = l2v; pid = 2; }
        if (l3  > bb) { bb = l3;  pid = 3; }
        if (lg4 > bb) { bb = lg4; pid = 4; }

        unsigned bal = __ballot_sync(0xffffffffu, pid == pt);
        int buf = kk & 1;
        if (lane == 0) wsum[buf][wid] = __popc(bal);
        __syncthreads();
        if (t == 0) {
            int cnt = wsum[buf][0] + wsum[buf][1] + wsum[buf][2] + wsum[buf][3];
            int enc = (cnt << 16) | (G2 - 1 - k);
            if (enc > bestEnc) bestEnc = enc;
        }
    }
    if (t == 0) atomicMax(&g_best, bestEnc);
}

// ---------------------------------------------------------------------------
// Kernel 2: decode best cell + finalize outputs (and reset g_best).
// (identical to measured round-6 version: 25.9us, 56 regs)
// out: [0..127] class_, [128..383] ph (N x 2), [384] max_num, [385..386] pos
// ---------------------------------------------------------------------------
__global__ __launch_bounds__(128)
void kfinal(const float* __restrict__ x,
            const float* __restrict__ w1, const float* __restrict__ b1,
            const float* __restrict__ g1, const float* __restrict__ be1,
            const float* __restrict__ m1, const float* __restrict__ v1,
            const float* __restrict__ w2, const float* __restrict__ b2,
            const float* __restrict__ g2, const float* __restrict__ be2,
            const float* __restrict__ m2, const float* __restrict__ v2,
            const float* __restrict__ w3, const float* __restrict__ b3,
            float* __restrict__ out)
{
    __shared__ int sbest;
    const int t = threadIdx.x;

    if (t == 0) {
        sbest = g_best;
        g_best = 0;              // reset for next graph replay (deterministic)
    }
    __syncthreads();
    const int best = sbest;
    const int bk = (G2 - 1) - (best & 0xFFFF);
    const int bn = best >> 16;

    if (t == 0) {
        out[384] = (float)bn;
        out[385] = grid_lon_f(bk);
        out[386] = grid_lat_f(bk);
    }

    {
        float lon2 = x[t * 4 + 0] * D2R;
        float lat2 = x[t * 4 + 1] * D2R;
        float s2 = sinf(lat2), c2 = cosf(lat2);
        float tc = x[t * 4 + 2] / 100.0f;

        float lat1 = grid_lat_f(bk) * D2R;
        float lon1 = grid_lon_f(bk) * D2R;
        float s1 = sinf(lat1), c1 = cosf(lat1);
        float dl  = lon2 - lon1;
        float sdl = sinf(dl), cdl = cosf(dl);
        float A  = c2 * sdl;
        float B  = c1 * s2 - s1 * c2 * cdl;
        float yv = sqrtf(A * A + B * B);
        float xv = s1 * s2 + c1 * c2 * cdl;
        float gd = atan2f(yv, xv) * 6371.0f;
        float d  = gd / 100.0f;

        float h1[32];
        for (int j = 0; j < 32; j++) {
            float z = d * w1[j] + tc * w1[32 + j] + b1[j];
            z = g1[j] * (z - m1[j]) / sqrtf(v1[j] + 1e-5f) + be1[j];
            h1[j] = xla_tanh(z);
        }
        float h2[32];
        for (int j = 0; j < 32; j++) {
            float z = b2[j];
            for (int i = 0; i < 32; i++) z += h1[i] * w2[i * 32 + j];
            z = g2[j] * (z - m2[j]) / sqrtf(v2[j] + 1e-5f) + be2[j];
            h2[j] = xla_tanh(z);
        }
        float lg[5];
        for (int c = 0; c < 5; c++) {
            float z = b3[c];
            for (int j = 0; j < 32; j++) z += h2[j] * w3[j * 5 + c];
            lg[c] = z;
        }
        int pid = 0; float bb = lg[0];
        for (int c = 1; c < 5; c++) if (lg[c] > bb) { bb = lg[c]; pid = c; }

        out[t] = (float)pid;
        out[128 + 2 * t + 0] = d * 100.0f;
        out[128 + 2 * t + 1] = tc * 100.0f;
    }
}

// ---------------------------------------------------------------------------
extern "C" void kernel_launch(void* const* d_in, const int* in_sizes, int n_in,
                              void* d_out, int out_size)
{
    const float* x   = (const float*)d_in[0];
    const float* w1  = (const float*)d_in[1];
    const float* b1  = (const float*)d_in[2];
    const float* g1  = (const float*)d_in[3];
    const float* be1 = (const float*)d_in[4];
    const float* m1  = (const float*)d_in[5];
    const float* v1  = (const float*)d_in[6];
    const float* w2  = (const float*)d_in[7];
    const float* b2  = (const float*)d_in[8];
    const float* g2  = (const float*)d_in[9];
    const float* be2 = (const float*)d_in[10];
    const float* m2  = (const float*)d_in[11];
    const float* v2  = (const float*)d_in[12];
    const float* w3  = (const float*)d_in[13];
    const float* b3  = (const float*)d_in[14];
    float* out = (float*)d_out;

    knum<<<G2 / KB, 128>>>(x, w1, b1, g1, be1, m1, v1,
                           w2, b2, g2, be2, m2, v2, w3, b3);
    kfinal<<<1, 128>>>(x, w1, b1, g1, be1, m1, v1,
                       w2, b2, g2, be2, m2, v2, w3, b3, out);
}

// round 9
// speedup vs baseline: 10.2625x; 1.0338x over previous
#include <cuda_runtime.h>
#include <math.h>

#define GSZ   200
#define G2    40000
#define NPT   128
#define KB    10     // grid cells per block (divides GSZ -> one lat row per block)

typedef unsigned long long u64;

__device__ int g_best;   // packed (num<<16)|(39999-k); reset to 0 by kfinal

// ---------------- f32x2 helpers (per-element IEEE rn) -----------------------
__device__ __forceinline__ u64 pk(float a, float b) {
    u64 r; asm("mov.b64 %0, {%1, %2};" : "=l"(r) : "f"(a), "f"(b)); return r;
}
__device__ __forceinline__ void upk(u64 v, float& a, float& b) {
    asm("mov.b64 {%0, %1}, %2;" : "=f"(a), "=f"(b) : "l"(v));
}
__device__ __forceinline__ u64 fma2(u64 a, u64 b, u64 c) {
    u64 r; asm("fma.rn.f32x2 %0, %1, %2, %3;" : "=l"(r) : "l"(a), "l"(b), "l"(c)); return r;
}

// ---------------------------------------------------------------------------
// XLA f32 tanh (Eigen rational) — exact scalar form (kfinal only)
// ---------------------------------------------------------------------------
__device__ __forceinline__ float xla_tanh(float x) {
    const float kClamp = 7.90531110763549805f;
    float xc = fminf(fmaxf(x, -kClamp), kClamp);
    float x2 = xc * xc;
    float p = fmaf(x2, -2.76076847742355e-16f, 2.00018790482477e-13f);
    p = fmaf(x2, p, -8.60467152213735e-11f);
    p = fmaf(x2, p,  5.12229709037114e-08f);
    p = fmaf(x2, p,  1.48572235717979e-05f);
    p = fmaf(x2, p,  6.37261928875436e-04f);
    p = fmaf(x2, p,  4.89352455891786e-03f);
    float q = fmaf(x2, 1.19825839466702e-06f, 1.18534705686654e-04f);
    q = fmaf(x2, q, 2.26843463243900e-03f);
    q = fmaf(x2, q, 4.89352518554385e-03f);
    float r = (xc * p) / q;
    return (fabsf(x) < 0.0004f) ? x : r;
}

// Fast tanh for knum: tanh(z) = 1 - 2/(exp2(z*2log2e)+1), NR-refined rcp.
// Error ~1e-7 class (same as proven-safe fast div). 5 FMA-class + 2 MUFU.
__device__ __forceinline__ float fast_tanh(float z) {
    float t = z * 2.8853900817779268f;          // 2/ln(2)
    t = fminf(fmaxf(t, -126.0f), 126.0f);       // keep e finite (NaN guard)
    float e; asm("ex2.approx.f32 %0, %1;" : "=f"(e) : "f"(t));
    float s = e + 1.0f;
    float r; asm("rcp.approx.f32 %0, %1;" : "=f"(r) : "f"(s));
    r = r * (2.0f - s * r);                      // Newton refinement
    return fmaf(-2.0f, r, 1.0f);
}

__device__ __forceinline__ float grid_lon_f(int k) {
    const float dlon = (float)((109.4132 - 95.987) / 200.0);
    return __fadd_rn(95.987f, __fmul_rn(dlon, (float)(k % GSZ)));
}
__device__ __forceinline__ float grid_lat_f(int k) {
    const float dlat = (float)((42.879 - 31.3039) / 200.0);
    return __fadd_rn(31.3039f, __fmul_rn(dlat, (float)(k / GSZ)));
}

#define D2R ((float)(3.14159265358979323846 / 180.0))

// ---------------------------------------------------------------------------
// Kernel 1: per-grid-cell agreement counts + fused packed-argmax atomic.
// ---------------------------------------------------------------------------
__global__ __launch_bounds__(128)
void knum(const float* __restrict__ x,
          const float* __restrict__ w1, const float* __restrict__ b1,
          const float* __restrict__ g1, const float* __restrict__ be1,
          const float* __restrict__ m1, const float* __restrict__ v1,
          const float* __restrict__ w2, const float* __restrict__ b2,
          const float* __restrict__ g2, const float* __restrict__ be2,
          const float* __restrict__ m2, const float* __restrict__ v2,
          const float* __restrict__ w3, const float* __restrict__ b3)
{
    __shared__ __align__(16) float w2s[32][32];   // [i][j] = a2[j]*w2[i*32+j]
    __shared__ __align__(16) float o2s[32];
    __shared__ float u1s[32], u2s[32], u0s[32];
    __shared__ u64  w3p01[32], w3p23[32];
    __shared__ float w3l[32], b3s[8];
    __shared__ int   wsum[2][4];

    const int t = threadIdx.x;

    if (t < 32) {
        float a1 = g1[t] / sqrtf(v1[t] + 1e-5f);
        u1s[t] = a1 * w1[t];
        u2s[t] = a1 * w1[32 + t];
        u0s[t] = fmaf(a1, b1[t], be1[t] - a1 * m1[t]);
        float a2 = g2[t] / sqrtf(v2[t] + 1e-5f);
        o2s[t] = fmaf(a2, b2[t], be2[t] - a2 * m2[t]);
        for (int i = 0; i < 32; i++) w2s[i][t] = a2 * w2[i * 32 + t];
        w3p01[t] = pk(w3[t * 5 + 0], w3[t * 5 + 1]);
        w3p23[t] = pk(w3[t * 5 + 2], w3[t * 5 + 3]);
        w3l[t]   = w3[t * 5 + 4];
        if (t < 5) b3s[t] = b3[t];
    }
    __syncthreads();

    // Per-point precompute.
    float lon2 = x[t * 4 + 0] * D2R;
    float lat2 = x[t * 4 + 1] * D2R;
    float s2 = sinf(lat2), c2 = cosf(lat2);
    float tc = x[t * 4 + 2] / 100.0f;
    int   pt = (int)x[t * 4 + 3];

    float p1[32];
#pragma unroll
    for (int j = 0; j < 32; j++) p1[j] = fmaf(tc, u2s[j], u0s[j]);

    const int lane = t & 31, wid = t >> 5;
    const int kbase = blockIdx.x * KB;

    // Row-constant haversine terms (all KB cells share one lat row).
    float lat1 = grid_lat_f(kbase) * D2R;
    float s1 = sinf(lat1), c1 = cosf(lat1);
    float t1 = c1 * s2, t2 = s1 * c2;     // B = t1 - t2*cdl
    float t3 = s1 * s2, t4 = c1 * c2;     // xv = t3 + t4*cdl

    const u64 lg01_0 = pk(b3s[0], b3s[1]);
    const u64 lg23_0 = pk(b3s[2], b3s[3]);
    const float lg4_0 = b3s[4];

    int bestEnc = 0;

#pragma unroll 1
    for (int kk = 0; kk < KB; kk++) {
        int k = kbase + kk;
        float lon1 = grid_lon_f(k) * D2R;
        float dl = lon2 - lon1;
        float sdl, cdl;
        sincosf(dl, &sdl, &cdl);
        float A  = c2 * sdl;
        float B  = t1 - t2 * cdl;
        float yv = sqrtf(A * A + B * B);
        float xv = t3 + t4 * cdl;
        float gd = atan2f(yv, xv) * 6371.0f;
        float d  = gd / 100.0f;

        // layer 1 (scalar fast tanh; MUFU-heavy, FMA-light)
        float h1[32];
#pragma unroll
        for (int j = 0; j < 32; j++)
            h1[j] = fast_tanh(fmaf(d, u1s[j], p1[j]));

        // layer 2: packed accumulate over output pairs, sequential i
        u64 acc[16];
        const u64* o2p = (const u64*)o2s;
#pragma unroll
        for (int jj = 0; jj < 16; jj++) acc[jj] = o2p[jj];
#pragma unroll
        for (int i = 0; i < 32; i++) {
            u64 hd = pk(h1[i], h1[i]);
            const u64* wrow = (const u64*)(w2s[i]);
#pragma unroll
            for (int jj = 0; jj < 16; jj++)
                acc[jj] = fma2(hd, wrow[jj], acc[jj]);
        }

        // layer-2 tanh + logits (class-pair packed)
        u64 lg01 = lg01_0, lg23 = lg23_0;
        float lg4 = lg4_0;
#pragma unroll
        for (int jj = 0; jj < 16; jj++) {
            float a0, a1v;
            upk(acc[jj], a0, a1v);
            float h20 = fast_tanh(a0);
            float h21 = fast_tanh(a1v);
            u64 hd0 = pk(h20, h20);
            u64 hd1 = pk(h21, h21);
            lg01 = fma2(hd0, w3p01[2 * jj + 0], lg01);
            lg23 = fma2(hd0, w3p23[2 * jj + 0], lg23);
            lg4  = fmaf(h20, w3l[2 * jj + 0], lg4);
            lg01 = fma2(hd1, w3p01[2 * jj + 1], lg01);
            lg23 = fma2(hd1, w3p23[2 * jj + 1], lg23);
            lg4  = fmaf(h21, w3l[2 * jj + 1], lg4);
        }

        float l0, l1, l2v, l3;
        upk(lg01, l0, l1);
        upk(lg23, l2v, l3);

        // first-max argmax over 5 logits
        int pid = 0; float bb = l0;
        if (l1  > bb) { bb = l1;  pid = 1; }
        if (l2v > bb) { bb = l2v; pid = 2; }
        if (l3  > bb) { bb = l3;  pid = 3; }
        if (lg4 > bb) { bb = lg4; pid = 4; }

        unsigned bal = __ballot_sync(0xffffffffu, pid == pt);
        int buf = kk & 1;
        if (lane == 0) wsum[buf][wid] = __popc(bal);
        __syncthreads();
        if (t == 0) {
            int cnt = wsum[buf][0] + wsum[buf][1] + wsum[buf][2] + wsum[buf][3];
            int enc = (cnt << 16) | (G2 - 1 - k);
            if (enc > bestEnc) bestEnc = enc;
        }
    }
    if (t == 0) atomicMax(&g_best, bestEnc);
}

// ---------------------------------------------------------------------------
// Kernel 2: decode best cell + finalize outputs (and reset g_best).
// Weights staged in smem with ROLLED loops (keeps regs ~56; kills the
// serial L2-latency LDG chain). Math identical to measured R6 version.
// out: [0..127] class_, [128..383] ph (N x 2), [384] max_num, [385..386] pos
// ---------------------------------------------------------------------------
__global__ __launch_bounds__(128)
void kfinal(const float* __restrict__ x,
            const float* __restrict__ w1, const float* __restrict__ b1,
            const float* __restrict__ g1, const float* __restrict__ be1,
            const float* __restrict__ m1, const float* __restrict__ v1,
            const float* __restrict__ w2, const float* __restrict__ b2,
            const float* __restrict__ g2, const float* __restrict__ be2,
            const float* __restrict__ m2, const float* __restrict__ v2,
            const float* __restrict__ w3, const float* __restrict__ b3,
            float* __restrict__ out)
{
    __shared__ float w2sh[1024];
    __shared__ float w1sh[64], w3sh[160];
    __shared__ float p1sh[32 * 5];     // b1,g1,be1,m1,v1
    __shared__ float p2sh[32 * 5];     // b2,g2,be2,m2,v2
    __shared__ float b3s[5];
    __shared__ int sbest;
    const int t = threadIdx.x;

    if (t == 0) {
        sbest = g_best;
        g_best = 0;              // reset for next graph replay (deterministic)
    }
    for (int i = t; i < 1024; i += 128) w2sh[i] = w2[i];
    if (t < 64) w1sh[t] = w1[t];
    for (int i = t; i < 160; i += 128) w3sh[i] = w3[i];
    if (t < 32) {
        p1sh[t]       = b1[t];  p1sh[32 + t] = g1[t]; p1sh[64 + t] = be1[t];
        p1sh[96 + t]  = m1[t];  p1sh[128 + t] = v1[t];
        p2sh[t]       = b2[t];  p2sh[32 + t] = g2[t]; p2sh[64 + t] = be2[t];
        p2sh[96 + t]  = m2[t];  p2sh[128 + t] = v2[t];
    }
    if (t < 5) b3s[t] = b3[t];
    __syncthreads();

    const int best = sbest;
    const int bk = (G2 - 1) - (best & 0xFFFF);
    const int bn = best >> 16;

    if (t == 0) {
        out[384] = (float)bn;
        out[385] = grid_lon_f(bk);
        out[386] = grid_lat_f(bk);
    }

    {
        float lon2 = x[t * 4 + 0] * D2R;
        float lat2 = x[t * 4 + 1] * D2R;
        float s2 = sinf(lat2), c2 = cosf(lat2);
        float tc = x[t * 4 + 2] / 100.0f;

        float lat1 = grid_lat_f(bk) * D2R;
        float lon1 = grid_lon_f(bk) * D2R;
        float s1 = sinf(lat1), c1 = cosf(lat1);
        float dl  = lon2 - lon1;
        float sdl = sinf(dl), cdl = cosf(dl);
        float A  = c2 * sdl;
        float B  = c1 * s2 - s1 * c2 * cdl;
        float yv = sqrtf(A * A + B * B);
        float xv = s1 * s2 + c1 * c2 * cdl;
        float gd = atan2f(yv, xv) * 6371.0f;
        float d  = gd / 100.0f;

        float h1[32];
        for (int j = 0; j < 32; j++) {
            float z = d * w1sh[j] + tc * w1sh[32 + j] + p1sh[j];
            z = p1sh[32 + j] * (z - p1sh[96 + j]) / sqrtf(p1sh[128 + j] + 1e-5f) + p1sh[64 + j];
            h1[j] = xla_tanh(z);
        }
        float h2[32];
        for (int j = 0; j < 32; j++) {
            float z = p2sh[j];
            for (int i = 0; i < 32; i++) z += h1[i] * w2sh[i * 32 + j];
            z = p2sh[32 + j] * (z - p2sh[96 + j]) / sqrtf(p2sh[128 + j] + 1e-5f) + p2sh[64 + j];
            h2[j] = xla_tanh(z);
        }
        float lg[5];
        for (int c = 0; c < 5; c++) {
            float z = b3s[c];
            for (int j = 0; j < 32; j++) z += h2[j] * w3sh[j * 5 + c];
            lg[c] = z;
        }
        int pid = 0; float bb = lg[0];
        for (int c = 1; c < 5; c++) if (lg[c] > bb) { bb = lg[c]; pid = c; }

        out[t] = (float)pid;
        out[128 + 2 * t + 0] = d * 100.0f;
        out[128 + 2 * t + 1] = tc * 100.0f;
    }
}

// ---------------------------------------------------------------------------
extern "C" void kernel_launch(void* const* d_in, const int* in_sizes, int n_in,
                              void* d_out, int out_size)
{
    const float* x   = (const float*)d_in[0];
    const float* w1  = (const float*)d_in[1];
    const float* b1  = (const float*)d_in[2];
    const float* g1  = (const float*)d_in[3];
    const float* be1 = (const float*)d_in[4];
    const float* m1  = (const float*)d_in[5];
    const float* v1  = (const float*)d_in[6];
    const float* w2  = (const float*)d_in[7];
    const float* b2  = (const float*)d_in[8];
    const float* g2  = (const float*)d_in[9];
    const float* be2 = (const float*)d_in[10];
    const float* m2  = (const float*)d_in[11];
    const float* v2  = (const float*)d_in[12];
    const float* w3  = (const float*)d_in[13];
    const float* b3  = (const float*)d_in[14];
    float* out = (float*)d_out;

    knum<<<G2 / KB, 128>>>(x, w1, b1, g1, be1, m1, v1,
                           w2, b2, g2, be2, m2, v2, w3, b3);
    kfinal<<<1, 128>>>(x, w1, b1, g1, be1, m1, v1,
                       w2, b2, g2, be2, m2, v2, w3, b3, out);
}